// round 12
// baseline (speedup 1.0000x reference)
#include <cuda_runtime.h>
#include <stdint.h>
#include <math.h>

// Problem constants: B=4, S=2048, D=1024, H=16, dh=64
#define BATCH 4
#define SEQ   2048
#define DMODEL 1024
#define NHEAD 16
#define DHEAD 64

// Scratch (alloc-free rule: __device__ globals)
__device__ float g_Q[(size_t)BATCH * NHEAD * SEQ * DHEAD]; // [b][h][s][d] tf32
__device__ float g_K[(size_t)BATCH * NHEAD * SEQ * DHEAD]; // tf32
__device__ float g_V[(size_t)BATCH * NHEAD * SEQ * DHEAD]; // tf32
__device__ float g_A[(size_t)BATCH * SEQ * DMODEL];        // attn out, tf32
__device__ float g_Xr[(size_t)BATCH * SEQ * DMODEL];       // tf32-rounded x
__device__ float g_Wqr[(size_t)DMODEL * DMODEL];
__device__ float g_Wkr[(size_t)DMODEL * DMODEL];
__device__ float g_Wvr[(size_t)DMODEL * DMODEL];
__device__ float g_Wor[(size_t)DMODEL * DMODEL];

// ---------------------------------------------------------------------------
// Helpers
// ---------------------------------------------------------------------------
__device__ __forceinline__ void cp16(uint32_t dst, const void* src) {
    asm volatile("cp.async.cg.shared.global [%0], [%1], 16;" :: "r"(dst), "l"(src));
}

__device__ __forceinline__ float tf32r(float x) {
    uint32_t u;
    asm("cvt.rna.tf32.f32 %0, %1;" : "=r"(u) : "f"(x));
    return __uint_as_float(u);
}

__device__ __forceinline__ void mma_tf32(float c[4], const uint32_t a[4],
                                         const uint32_t b[2]) {
    asm volatile(
        "mma.sync.aligned.m16n8k8.row.col.f32.tf32.tf32.f32 "
        "{%0,%1,%2,%3}, {%4,%5,%6,%7}, {%8,%9}, {%0,%1,%2,%3};"
        : "+f"(c[0]), "+f"(c[1]), "+f"(c[2]), "+f"(c[3])
        : "r"(a[0]), "r"(a[1]), "r"(a[2]), "r"(a[3]), "r"(b[0]), "r"(b[1]));
}

// ---------------------------------------------------------------------------
// Pre-round pass: x and all 4 weights -> tf32(RNA) scratch (float4 vectorized)
// ---------------------------------------------------------------------------
#define XR_F4 ((size_t)BATCH * SEQ * DMODEL / 4)   // 2M float4
#define W_F4  ((size_t)DMODEL * DMODEL / 4)        // 256K float4
#define RP_TOTAL (XR_F4 + 4 * W_F4)                // 3M float4

__global__ __launch_bounds__(256) void round_pass(
    const float4* __restrict__ x,  const float4* __restrict__ wq,
    const float4* __restrict__ wk, const float4* __restrict__ wv,
    const float4* __restrict__ wo)
{
    size_t i = (size_t)blockIdx.x * blockDim.x + threadIdx.x;
    if (i >= RP_TOTAL) return;
    const float4* src; float4* dst; size_t j;
    if (i < XR_F4)                { src = x;  dst = (float4*)g_Xr;  j = i; }
    else {
        size_t k = i - XR_F4; int sel = (int)(k / W_F4); j = k % W_F4;
        src = (sel == 0) ? wq : (sel == 1) ? wk : (sel == 2) ? wv : wo;
        dst = (float4*)((sel == 0) ? g_Wqr : (sel == 1) ? g_Wkr
                       : (sel == 2) ? g_Wvr : g_Wor);
    }
    float4 v = src[j];
    dst[j] = make_float4(tf32r(v.x), tf32r(v.y), tf32r(v.z), tf32r(v.w));
}

// ---------------------------------------------------------------------------
// TF32 tensor-core GEMM (R11 core, now 2 CTAs/SM for latency hiding).
// C[m][n] = sum_k A[m][k] * W[n][k]. 128x128 tile, BK=32, 8 warps (2m x 4n).
// Smem elem (r,k) at float idx r*32 + ((k>>2)^(r&7))*4 + (k&3).
// MODE 0: z selects Q/K/V weights; epilogue fuses RoPE, stores tf32-rounded,
//         scatters to [b][h][s][dh]. MODE 1: plain row-major store to out.
// ---------------------------------------------------------------------------
template <int MODE>
__global__ __launch_bounds__(256, 2) void gemm_tf32(float* __restrict__ Cout)
{
    extern __shared__ float gsm[];          // 64KB: A0, B0, A1, B1 (16KB each)
    const int z = (MODE == 0) ? blockIdx.z : 0;
    const float* Ain = (MODE == 0) ? g_Xr : g_A;
    const float* W = (MODE == 0) ? ((z == 0) ? g_Wqr : (z == 1) ? g_Wkr : g_Wvr)
                                 : g_Wor;
    float* Out = (MODE == 0) ? ((z == 0) ? g_Q : (z == 1) ? g_K : g_V) : Cout;

    const int m0 = blockIdx.y * 128, n0 = blockIdx.x * 128;
    const int t = threadIdx.x;
    const int lane = t & 31, wid = t >> 5;
    const int wm = wid >> 2, wn = wid & 3;
    const int gi = lane >> 2, ti = lane & 3;

    float* Ab[2] = {gsm, gsm + 8192};
    float* Bb[2] = {gsm + 4096, gsm + 12288};
    uint32_t sb;
    asm("{ .reg .u64 u; cvta.to.shared.u64 u, %1; cvt.u32.u64 %0, u; }"
        : "=r"(sb) : "l"(gsm));
    const uint32_t aoff0 = sb, aoff1 = sb + 8192 * 4;
    const uint32_t boff0 = sb + 4096 * 4, boff1 = sb + 12288 * 4;

    const int rr = t >> 3, cg = t & 7;
    const float* Ag = Ain + (size_t)(m0 + rr) * DMODEL + cg * 4;
    const float* Bg = W + (size_t)(n0 + rr) * DMODEL + cg * 4;
    const uint32_t dsw = (uint32_t)(rr * 32 + ((cg ^ (rr & 7)) << 2)) * 4;

    // Per-lane fragment row bases (float index). row&7 == gi for all rows.
    int aBase[4], bBase[4];
    #pragma unroll
    for (int mi = 0; mi < 4; mi++) aBase[mi] = (wm * 64 + mi * 16 + gi) * 32 + ti;
    #pragma unroll
    for (int ni = 0; ni < 4; ni++) bBase[ni] = (wn * 32 + ni * 8 + gi) * 32 + ti;

    float acc[4][4][4];
    #pragma unroll
    for (int mi = 0; mi < 4; mi++)
        #pragma unroll
        for (int ni = 0; ni < 4; ni++)
            #pragma unroll
            for (int c = 0; c < 4; c++) acc[mi][ni][c] = 0.0f;

    auto stage = [&](int buf, int kt) {
        const float* ag = Ag + kt * 32;
        const float* bg = Bg + kt * 32;
        uint32_t ad = (buf ? aoff1 : aoff0) + dsw;
        uint32_t bd = (buf ? boff1 : boff0) + dsw;
        #pragma unroll
        for (int i = 0; i < 4; i++) {
            cp16(ad + i * 4096, ag + (size_t)i * 32 * DMODEL);
            cp16(bd + i * 4096, bg + (size_t)i * 32 * DMODEL);
        }
        asm volatile("cp.async.commit_group;");
    };

    stage(0, 0);
    for (int kt = 0; kt < DMODEL / 32; kt++) {
        const int buf = kt & 1;
        asm volatile("cp.async.wait_group 0;");
        __syncthreads();
        if (kt < DMODEL / 32 - 1) stage(buf ^ 1, kt + 1);

        const float* Sa = Ab[buf];
        const float* Sb = Bb[buf];
        #pragma unroll
        for (int ks = 0; ks < 4; ks++) {
            const int s0 = ((2 * ks) ^ gi) << 2;        // k-group 2ks slot
            const int s1 = ((2 * ks + 1) ^ gi) << 2;    // k-group 2ks+1 slot
            uint32_t af[4][4];
            #pragma unroll
            for (int mi = 0; mi < 4; mi++) {
                af[mi][0] = __float_as_uint(Sa[aBase[mi] + s0]);
                af[mi][1] = __float_as_uint(Sa[aBase[mi] + 256 + s0]);
                af[mi][2] = __float_as_uint(Sa[aBase[mi] + s1]);
                af[mi][3] = __float_as_uint(Sa[aBase[mi] + 256 + s1]);
            }
            uint32_t bf[4][2];
            #pragma unroll
            for (int ni = 0; ni < 4; ni++) {
                bf[ni][0] = __float_as_uint(Sb[bBase[ni] + s0]);
                bf[ni][1] = __float_as_uint(Sb[bBase[ni] + s1]);
            }
            #pragma unroll
            for (int mi = 0; mi < 4; mi++)
                #pragma unroll
                for (int ni = 0; ni < 4; ni++)
                    mma_tf32(acc[mi][ni], af[mi], bf[ni]);
        }
    }

    // Epilogue. c0=(r,c), c1=(r,c+1), c2=(r+8,c), c3=(r+8,c+1); c even.
    #pragma unroll
    for (int mi = 0; mi < 4; mi++) {
        #pragma unroll
        for (int ni = 0; ni < 4; ni++) {
            const int row = m0 + wm * 64 + mi * 16 + gi;
            const int col = n0 + wn * 32 + ni * 8 + 2 * ti;
            const float c0 = acc[mi][ni][0], c1 = acc[mi][ni][1];
            const float c2 = acc[mi][ni][2], c3 = acc[mi][ni][3];
            if (MODE == 1) {
                *(float2*)(Out + (size_t)row * DMODEL + col) = make_float2(c0, c1);
                *(float2*)(Out + (size_t)(row + 8) * DMODEL + col) = make_float2(c2, c3);
            } else {
                const int h = col >> 6, dq = col & 63;
                const int s0 = row & (SEQ - 1), bb = row >> 11;
                float* d0 = Out + (((size_t)(bb * NHEAD + h) * SEQ + s0) * DHEAD + dq);
                float* d1 = d0 + 8 * DHEAD;
                if (z < 2) {
                    const int fi = dq >> 1;
                    const float inv = exp2f(-0.41524101186092356f * (float)fi);
                    float sn, cs;
                    sincosf((float)s0 * inv, &sn, &cs);
                    *(float2*)d0 = make_float2(tf32r(c0 * cs - c1 * sn),
                                               tf32r(c0 * sn + c1 * cs));
                    sincosf((float)(s0 + 8) * inv, &sn, &cs);
                    *(float2*)d1 = make_float2(tf32r(c2 * cs - c3 * sn),
                                               tf32r(c2 * sn + c3 * cs));
                } else {
                    *(float2*)d0 = make_float2(tf32r(c0), tf32r(c1));
                    *(float2*)d1 = make_float2(tf32r(c2), tf32r(c3));
                }
            }
        }
    }
}

// ---------------------------------------------------------------------------
// Tensor-core flash attention (tf32), unchanged from passing R11.
// ---------------------------------------------------------------------------
#define FBQ 128
#define FBK 64
#define PADK 68
#define PADV 72
#define FLASH_SMEM_FLOATS (128*PADK + 64*PADK + 64*PADV + 8*16*PADK)

__global__ __launch_bounds__(256, 2) void flash_tc()
{
    extern __shared__ float sm[];
    float* Qs = sm;                          // [128][68]
    float* Ks = Qs + 128 * PADK;             // [64][68]
    float* Vs = Ks + 64 * PADK;              // [64][72]
    float* Ps = Vs + 64 * PADV;              // [8][16][68]

    const int qt = (int)gridDim.x - 1 - (int)blockIdx.x;   // heavy blocks first
    const int bh = blockIdx.y;
    const float* Qb = g_Q + (size_t)bh * SEQ * DHEAD;
    const float* Kb = g_K + (size_t)bh * SEQ * DHEAD;
    const float* Vb = g_V + (size_t)bh * SEQ * DHEAD;

    const int tid = threadIdx.x;
    const int lane = tid & 31, w = tid >> 5;
    const int gi = lane >> 2, ti = lane & 3;
    const int q0 = qt * FBQ;
    const int wq0 = q0 + w * 16;
    float* Pw = Ps + w * 16 * PADK;

    {
        const int r = tid >> 1;
        const int cb = (tid & 1) * 32;
        #pragma unroll
        for (int j = 0; j < 8; j++) {
            float4 v = *(const float4*)(Qb + (size_t)(q0 + r) * DHEAD + cb + j * 4);
            *(float4*)&Qs[r * PADK + cb + j * 4] =
                make_float4(v.x * 0.125f, v.y * 0.125f, v.z * 0.125f, v.w * 0.125f);
        }
    }

    float oacc[8][4];
    #pragma unroll
    for (int nt = 0; nt < 8; nt++)
        #pragma unroll
        for (int c = 0; c < 4; c++) oacc[nt][c] = 0.0f;
    float m0 = -1e30f, m1 = -1e30f, l0 = 0.0f, l1 = 0.0f;

    const int nkt = 2 * (qt + 1);
    for (int kt = 0; kt < nkt; kt++) {
        const int k0 = kt * FBK;
        __syncthreads();
        {
            const int r = tid >> 2;
            const int cb = (tid & 3) * 16;
            #pragma unroll
            for (int j = 0; j < 4; j++) {
                *(float4*)&Ks[r * PADK + cb + j * 4] =
                    *(const float4*)(Kb + (size_t)(k0 + r) * DHEAD + cb + j * 4);
                *(float4*)&Vs[r * PADV + cb + j * 4] =
                    *(const float4*)(Vb + (size_t)(k0 + r) * DHEAD + cb + j * 4);
            }
        }
        __syncthreads();

        float sfr[8][4];
        #pragma unroll
        for (int nt = 0; nt < 8; nt++)
            #pragma unroll
            for (int c = 0; c < 4; c++) sfr[nt][c] = 0.0f;

        #pragma unroll
        for (int kc = 0; kc < 8; kc++) {
            const int kk = kc * 8 + ti;
            uint32_t af[4];
            af[0] = __float_as_uint(Qs[(w * 16 + gi) * PADK + kk]);
            af[1] = __float_as_uint(Qs[(w * 16 + gi + 8) * PADK + kk]);
            af[2] = __float_as_uint(Qs[(w * 16 + gi) * PADK + kk + 4]);
            af[3] = __float_as_uint(Qs[(w * 16 + gi + 8) * PADK + kk + 4]);
            #pragma unroll
            for (int nt = 0; nt < 8; nt++) {
                uint32_t bf[2];
                bf[0] = __float_as_uint(Ks[(nt * 8 + gi) * PADK + kk]);
                bf[1] = __float_as_uint(Ks[(nt * 8 + gi) * PADK + kk + 4]);
                mma_tf32(sfr[nt], af, bf);
            }
        }

        if (k0 + FBK - 1 > wq0) {
            const int r0 = wq0 + gi, r1 = wq0 + gi + 8;
            #pragma unroll
            for (int nt = 0; nt < 8; nt++) {
                const int col = k0 + nt * 8 + 2 * ti;
                if (col > r0)     sfr[nt][0] = -1e30f;
                if (col + 1 > r0) sfr[nt][1] = -1e30f;
                if (col > r1)     sfr[nt][2] = -1e30f;
                if (col + 1 > r1) sfr[nt][3] = -1e30f;
            }
        }

        float mx0 = -1e30f, mx1 = -1e30f;
        #pragma unroll
        for (int nt = 0; nt < 8; nt++) {
            mx0 = fmaxf(mx0, fmaxf(sfr[nt][0], sfr[nt][1]));
            mx1 = fmaxf(mx1, fmaxf(sfr[nt][2], sfr[nt][3]));
        }
        #pragma unroll
        for (int off = 1; off < 4; off <<= 1) {
            mx0 = fmaxf(mx0, __shfl_xor_sync(0xffffffffu, mx0, off));
            mx1 = fmaxf(mx1, __shfl_xor_sync(0xffffffffu, mx1, off));
        }
        const float mn0 = fmaxf(m0, mx0), mn1 = fmaxf(m1, mx1);
        const float al0 = __expf(m0 - mn0), al1 = __expf(m1 - mn1);
        m0 = mn0; m1 = mn1;

        float s0 = 0.0f, s1 = 0.0f;
        #pragma unroll
        for (int nt = 0; nt < 8; nt++) {
            sfr[nt][0] = __expf(sfr[nt][0] - mn0);
            sfr[nt][1] = __expf(sfr[nt][1] - mn0);
            sfr[nt][2] = __expf(sfr[nt][2] - mn1);
            sfr[nt][3] = __expf(sfr[nt][3] - mn1);
            s0 += sfr[nt][0] + sfr[nt][1];
            s1 += sfr[nt][2] + sfr[nt][3];
        }
        #pragma unroll
        for (int off = 1; off < 4; off <<= 1) {
            s0 += __shfl_xor_sync(0xffffffffu, s0, off);
            s1 += __shfl_xor_sync(0xffffffffu, s1, off);
        }
        l0 = l0 * al0 + s0;
        l1 = l1 * al1 + s1;
        #pragma unroll
        for (int nt = 0; nt < 8; nt++) {
            oacc[nt][0] *= al0; oacc[nt][1] *= al0;
            oacc[nt][2] *= al1; oacc[nt][3] *= al1;
        }

        #pragma unroll
        for (int nt = 0; nt < 8; nt++) {
            *(float2*)&Pw[gi * PADK + nt * 8 + 2 * ti] =
                make_float2(tf32r(sfr[nt][0]), tf32r(sfr[nt][1]));
            *(float2*)&Pw[(gi + 8) * PADK + nt * 8 + 2 * ti] =
                make_float2(tf32r(sfr[nt][2]), tf32r(sfr[nt][3]));
        }
        __syncwarp();

        #pragma unroll
        for (int kc = 0; kc < 8; kc++) {
            const int kk = kc * 8 + ti;
            uint32_t af[4];
            af[0] = __float_as_uint(Pw[gi * PADK + kk]);
            af[1] = __float_as_uint(Pw[(gi + 8) * PADK + kk]);
            af[2] = __float_as_uint(Pw[gi * PADK + kk + 4]);
            af[3] = __float_as_uint(Pw[(gi + 8) * PADK + kk + 4]);
            #pragma unroll
            for (int nt = 0; nt < 8; nt++) {
                uint32_t bf[2];
                bf[0] = __float_as_uint(Vs[kk * PADV + nt * 8 + gi]);
                bf[1] = __float_as_uint(Vs[(kk + 4) * PADV + nt * 8 + gi]);
                mma_tf32(oacc[nt], af, bf);
            }
        }
        __syncwarp();
    }

    // Normalize + store (tf32-rounded: feeds out GEMM with no in-loop cvt)
    const int b = bh >> 4, h = bh & 15;
    const float inv0 = 1.0f / l0, inv1 = 1.0f / l1;
    const int r0 = q0 + w * 16 + gi, r1 = r0 + 8;
    float* base0 = g_A + ((size_t)(b * SEQ + r0)) * DMODEL + h * DHEAD;
    float* base1 = g_A + ((size_t)(b * SEQ + r1)) * DMODEL + h * DHEAD;
    #pragma unroll
    for (int nt = 0; nt < 8; nt++) {
        const int col = nt * 8 + 2 * ti;
        *(float2*)(base0 + col) =
            make_float2(tf32r(oacc[nt][0] * inv0), tf32r(oacc[nt][1] * inv0));
        *(float2*)(base1 + col) =
            make_float2(tf32r(oacc[nt][2] * inv1), tf32r(oacc[nt][3] * inv1));
    }
}

// ---------------------------------------------------------------------------

extern "C" void kernel_launch(void* const* d_in, const int* in_sizes, int n_in,
                              void* d_out, int out_size)
{
    const float* x  = (const float*)d_in[0];
    const float* Wq = (const float*)d_in[1];
    const float* Wk = (const float*)d_in[2];
    const float* Wv = (const float*)d_in[3];
    const float* Wo = (const float*)d_in[4];
    float* out = (float*)d_out;

    cudaFuncSetAttribute(gemm_tf32<0>, cudaFuncAttributeMaxDynamicSharedMemorySize, 65536);
    cudaFuncSetAttribute(gemm_tf32<1>, cudaFuncAttributeMaxDynamicSharedMemorySize, 65536);
    cudaFuncSetAttribute(flash_tc, cudaFuncAttributeMaxDynamicSharedMemorySize,
                         FLASH_SMEM_FLOATS * (int)sizeof(float));

    round_pass<<<(unsigned)((RP_TOTAL + 255) / 256), 256>>>(
        (const float4*)x, (const float4*)Wq, (const float4*)Wk,
        (const float4*)Wv, (const float4*)Wo);

    dim3 g1(DMODEL / 128, (BATCH * SEQ) / 128, 3);
    gemm_tf32<0><<<g1, 256, 65536>>>(nullptr);

    flash_tc<<<dim3(SEQ / FBQ, BATCH * NHEAD), 256,
               FLASH_SMEM_FLOATS * (int)sizeof(float)>>>();

    dim3 g2(DMODEL / 128, (BATCH * SEQ) / 128, 1);
    gemm_tf32<1><<<g2, 256, 65536>>>(out);
}

// round 15
// speedup vs baseline: 1.3507x; 1.3507x over previous
#include <cuda_runtime.h>
#include <cuda_fp16.h>
#include <stdint.h>
#include <math.h>

// Problem constants: B=4, S=2048, D=1024, H=16, dh=64
#define BATCH 4
#define SEQ   2048
#define DMODEL 1024
#define NHEAD 16
#define DHEAD 64

// Scratch (alloc-free rule: __device__ globals)
__device__ float  g_Q[(size_t)BATCH * NHEAD * SEQ * DHEAD]; // [b][h][s][d] tf32
__device__ float  g_K[(size_t)BATCH * NHEAD * SEQ * DHEAD]; // tf32
__device__ float  g_V[(size_t)BATCH * NHEAD * SEQ * DHEAD]; // tf32
__device__ __half g_Ah[(size_t)BATCH * SEQ * DMODEL];       // attn out, fp16
__device__ __half g_Xh[(size_t)BATCH * SEQ * DMODEL];       // fp16-rounded x
__device__ __half g_Wqh[(size_t)DMODEL * DMODEL];
__device__ __half g_Wkh[(size_t)DMODEL * DMODEL];
__device__ __half g_Wvh[(size_t)DMODEL * DMODEL];
__device__ __half g_Woh[(size_t)DMODEL * DMODEL];

// ---------------------------------------------------------------------------
// Helpers
// ---------------------------------------------------------------------------
__device__ __forceinline__ void cp16(uint32_t dst, const void* src) {
    asm volatile("cp.async.cg.shared.global [%0], [%1], 16;" :: "r"(dst), "l"(src));
}

__device__ __forceinline__ float tf32r(float x) {
    uint32_t u;
    asm("cvt.rna.tf32.f32 %0, %1;" : "=r"(u) : "f"(x));
    return __uint_as_float(u);
}

// fp16 MMA, fp32 accum: m16n8k16
__device__ __forceinline__ void mma_f16(float c[4], const uint32_t a[4],
                                        const uint32_t b[2]) {
    asm volatile(
        "mma.sync.aligned.m16n8k16.row.col.f32.f16.f16.f32 "
        "{%0,%1,%2,%3}, {%4,%5,%6,%7}, {%8,%9}, {%0,%1,%2,%3};"
        : "+f"(c[0]), "+f"(c[1]), "+f"(c[2]), "+f"(c[3])
        : "r"(a[0]), "r"(a[1]), "r"(a[2]), "r"(a[3]), "r"(b[0]), "r"(b[1]));
}

// tf32 MMA (flash, unchanged)
__device__ __forceinline__ void mma_tf32(float c[4], const uint32_t a[4],
                                         const uint32_t b[2]) {
    asm volatile(
        "mma.sync.aligned.m16n8k8.row.col.f32.tf32.tf32.f32 "
        "{%0,%1,%2,%3}, {%4,%5,%6,%7}, {%8,%9}, {%0,%1,%2,%3};"
        : "+f"(c[0]), "+f"(c[1]), "+f"(c[2]), "+f"(c[3])
        : "r"(a[0]), "r"(a[1]), "r"(a[2]), "r"(a[3]), "r"(b[0]), "r"(b[1]));
}

__device__ __forceinline__ uint32_t smem_u32(const void* p) {
    uint32_t a;
    asm("{ .reg .u64 u; cvta.to.shared.u64 u, %1; cvt.u32.u64 %0, u; }"
        : "=r"(a) : "l"(p));
    return a;
}

// ---------------------------------------------------------------------------
// Pre-round pass: x + 4 weights -> fp16(RN) scratch. 4 floats per thread.
// ---------------------------------------------------------------------------
#define XR_F4 ((size_t)BATCH * SEQ * DMODEL / 4)   // 2M float4
#define W_F4  ((size_t)DMODEL * DMODEL / 4)        // 256K float4
#define RP_TOTAL (XR_F4 + 4 * W_F4)                // 3M float4

__global__ __launch_bounds__(256) void round_pass(
    const float4* __restrict__ x,  const float4* __restrict__ wq,
    const float4* __restrict__ wk, const float4* __restrict__ wv,
    const float4* __restrict__ wo)
{
    size_t i = (size_t)blockIdx.x * blockDim.x + threadIdx.x;
    if (i >= RP_TOTAL) return;
    const float4* src; __half2* dst; size_t j;
    if (i < XR_F4)                { src = x;  dst = (__half2*)g_Xh;  j = i; }
    else {
        size_t k = i - XR_F4; int sel = (int)(k / W_F4); j = k % W_F4;
        src = (sel == 0) ? wq : (sel == 1) ? wk : (sel == 2) ? wv : wo;
        dst = (__half2*)((sel == 0) ? g_Wqh : (sel == 1) ? g_Wkh
                        : (sel == 2) ? g_Wvh : g_Woh);
    }
    float4 v = src[j];
    dst[j * 2]     = __floats2half2_rn(v.x, v.y);
    dst[j * 2 + 1] = __floats2half2_rn(v.z, v.w);
}

// ---------------------------------------------------------------------------
// FP16 mma.sync GEMM (R11-proven skeleton; same byte layout, halfs in u32):
// C[m][n] = sum_k A[m][k] * W[n][k]. 128x128 tile, BK=64 halfs (128B rows,
// identical 16B-seg XOR swizzle), 8 warps 2m x 4n, m16n8k16.
// MODE 0: z selects Wq/Wk/Wv; epilogue fuses RoPE (z<2), stores tf32-rounded
//         fp32 to [b][h][s][dh]. MODE 1: A=g_Ah, W=g_Woh, fp32 store to out.
// SMEM 64KB: A0 16K | B0 16K | A1 16K | B1 16K.
// ---------------------------------------------------------------------------
#define GSM_BYTES 65536

template <int MODE>
__global__ __launch_bounds__(256) void gemm_fp16(float* __restrict__ Cout)
{
    extern __shared__ uint32_t gsm32[];
    const int z = (MODE == 0) ? blockIdx.z : 0;
    const __half* Ain = (MODE == 0) ? g_Xh : g_Ah;
    const __half* W = (MODE == 0) ? ((z == 0) ? g_Wqh : (z == 1) ? g_Wkh : g_Wvh)
                                  : g_Woh;
    float* Out = (MODE == 0) ? ((z == 0) ? g_Q : (z == 1) ? g_K : g_V) : Cout;

    const int m0 = blockIdx.y * 128, n0 = blockIdx.x * 128;
    const int t = threadIdx.x;
    const int lane = t & 31, wid = t >> 5;
    const int wm = wid >> 2, wn = wid & 3;      // 2m x 4n warps, tile 64x32
    const int gi = lane >> 2, ti = lane & 3;

    // u32 views per buffer (each tile 16KB = 4096 u32)
    uint32_t* Ab[2] = {gsm32, gsm32 + 8192};
    uint32_t* Bb[2] = {gsm32 + 4096, gsm32 + 12288};
    const uint32_t sb = smem_u32(gsm32);
    const uint32_t aoff0 = sb, aoff1 = sb + 32768u;
    const uint32_t boff0 = sb + 16384u, boff1 = sb + 49152u;

    const int rr = t >> 3, cg = t & 7;          // staging row 0..31, 16B seg
    const __half* Ag = Ain + (size_t)(m0 + rr) * DMODEL + cg * 8;
    const __half* Bg = W + (size_t)(n0 + rr) * DMODEL + cg * 8;
    const uint32_t dsw = (uint32_t)(rr * 32 + ((cg ^ (rr & 7)) << 2)) * 4;

    // Fragment row bases (u32 idx). row&7 == gi for all fragment rows.
    int aBase[4], bBase[4];
    #pragma unroll
    for (int mi = 0; mi < 4; mi++) aBase[mi] = (wm * 64 + mi * 16 + gi) * 32 + ti;
    #pragma unroll
    for (int ni = 0; ni < 4; ni++) bBase[ni] = (wn * 32 + ni * 8 + gi) * 32 + ti;

    float acc[4][4][4];
    #pragma unroll
    for (int mi = 0; mi < 4; mi++)
        #pragma unroll
        for (int ni = 0; ni < 4; ni++)
            #pragma unroll
            for (int c = 0; c < 4; c++) acc[mi][ni][c] = 0.0f;

    auto stage = [&](int buf, int kt) {
        const __half* ag = Ag + kt * 64;
        const __half* bg = Bg + kt * 64;
        uint32_t ad = (buf ? aoff1 : aoff0) + dsw;
        uint32_t bd = (buf ? boff1 : boff0) + dsw;
        #pragma unroll
        for (int i = 0; i < 4; i++) {
            cp16(ad + i * 4096, ag + (size_t)i * 32 * DMODEL);
            cp16(bd + i * 4096, bg + (size_t)i * 32 * DMODEL);
        }
        asm volatile("cp.async.commit_group;");
    };

    stage(0, 0);
    for (int kt = 0; kt < DMODEL / 64; kt++) {
        const int buf = kt & 1;
        asm volatile("cp.async.wait_group 0;");
        __syncthreads();
        if (kt < DMODEL / 64 - 1) stage(buf ^ 1, kt + 1);

        const uint32_t* Sa = Ab[buf];
        const uint32_t* Sb = Bb[buf];
        #pragma unroll
        for (int ks = 0; ks < 4; ks++) {            // each ks = k16 MMA step
            const int s0 = ((2 * ks) ^ gi) << 2;    // seg 2ks slot (k, k+...7)
            const int s1 = ((2 * ks + 1) ^ gi) << 2;// seg 2ks+1 slot (k+8..15)
            uint32_t af[4][4];
            #pragma unroll
            for (int mi = 0; mi < 4; mi++) {
                af[mi][0] = Sa[aBase[mi] + s0];          // (gi,   k..k+1)
                af[mi][1] = Sa[aBase[mi] + 256 + s0];    // (gi+8, k..k+1)
                af[mi][2] = Sa[aBase[mi] + s1];          // (gi,   k+8..k+9)
                af[mi][3] = Sa[aBase[mi] + 256 + s1];    // (gi+8, k+8..k+9)
            }
            uint32_t bf[4][2];
            #pragma unroll
            for (int ni = 0; ni < 4; ni++) {
                bf[ni][0] = Sb[bBase[ni] + s0];
                bf[ni][1] = Sb[bBase[ni] + s1];
            }
            #pragma unroll
            for (int mi = 0; mi < 4; mi++)
                #pragma unroll
                for (int ni = 0; ni < 4; ni++)
                    mma_f16(acc[mi][ni], af[mi], bf[ni]);
        }
    }

    // Epilogue. c0=(r,c), c1=(r,c+1), c2=(r+8,c), c3=(r+8,c+1); c even.
    #pragma unroll
    for (int mi = 0; mi < 4; mi++) {
        #pragma unroll
        for (int ni = 0; ni < 4; ni++) {
            const int row = m0 + wm * 64 + mi * 16 + gi;
            const int col = n0 + wn * 32 + ni * 8 + 2 * ti;
            const float c0 = acc[mi][ni][0], c1 = acc[mi][ni][1];
            const float c2 = acc[mi][ni][2], c3 = acc[mi][ni][3];
            if (MODE == 1) {
                *(float2*)(Out + (size_t)row * DMODEL + col) = make_float2(c0, c1);
                *(float2*)(Out + (size_t)(row + 8) * DMODEL + col) = make_float2(c2, c3);
            } else {
                const int h = col >> 6, dq = col & 63;
                const int s0 = row & (SEQ - 1), bb = row >> 11;
                float* d0 = Out + (((size_t)(bb * NHEAD + h) * SEQ + s0) * DHEAD + dq);
                float* d1 = d0 + 8 * DHEAD;     // row+8 same (b,h)
                if (z < 2) {
                    const int fi = dq >> 1;
                    const float inv = exp2f(-0.41524101186092356f * (float)fi);
                    float sn, cs;
                    sincosf((float)s0 * inv, &sn, &cs);
                    *(float2*)d0 = make_float2(tf32r(c0 * cs - c1 * sn),
                                               tf32r(c0 * sn + c1 * cs));
                    sincosf((float)(s0 + 8) * inv, &sn, &cs);
                    *(float2*)d1 = make_float2(tf32r(c2 * cs - c3 * sn),
                                               tf32r(c2 * sn + c3 * cs));
                } else {
                    *(float2*)d0 = make_float2(tf32r(c0), tf32r(c1));
                    *(float2*)d1 = make_float2(tf32r(c2), tf32r(c3));
                }
            }
        }
    }
}

// ---------------------------------------------------------------------------
// Tensor-core flash attention (tf32), R11-proven; only the final store changes
// to fp16 (g_Ah) feeding the fp16 out-projection.
// ---------------------------------------------------------------------------
#define FBQ 128
#define FBK 64
#define PADK 68
#define PADV 72
#define FLASH_SMEM_FLOATS (128*PADK + 64*PADK + 64*PADV + 8*16*PADK)

__global__ __launch_bounds__(256, 2) void flash_tc()
{
    extern __shared__ float sm[];
    float* Qs = sm;                          // [128][68]
    float* Ks = Qs + 128 * PADK;             // [64][68]
    float* Vs = Ks + 64 * PADK;              // [64][72]
    float* Ps = Vs + 64 * PADV;              // [8][16][68]

    const int qt = (int)gridDim.x - 1 - (int)blockIdx.x;   // heavy blocks first
    const int bh = blockIdx.y;
    const float* Qb = g_Q + (size_t)bh * SEQ * DHEAD;
    const float* Kb = g_K + (size_t)bh * SEQ * DHEAD;
    const float* Vb = g_V + (size_t)bh * SEQ * DHEAD;

    const int tid = threadIdx.x;
    const int lane = tid & 31, w = tid >> 5;
    const int gi = lane >> 2, ti = lane & 3;
    const int q0 = qt * FBQ;
    const int wq0 = q0 + w * 16;
    float* Pw = Ps + w * 16 * PADK;

    {
        const int r = tid >> 1;
        const int cb = (tid & 1) * 32;
        #pragma unroll
        for (int j = 0; j < 8; j++) {
            float4 v = *(const float4*)(Qb + (size_t)(q0 + r) * DHEAD + cb + j * 4);
            *(float4*)&Qs[r * PADK + cb + j * 4] =
                make_float4(v.x * 0.125f, v.y * 0.125f, v.z * 0.125f, v.w * 0.125f);
        }
    }

    float oacc[8][4];
    #pragma unroll
    for (int nt = 0; nt < 8; nt++)
        #pragma unroll
        for (int c = 0; c < 4; c++) oacc[nt][c] = 0.0f;
    float m0 = -1e30f, m1 = -1e30f, l0 = 0.0f, l1 = 0.0f;

    const int nkt = 2 * (qt + 1);
    for (int kt = 0; kt < nkt; kt++) {
        const int k0 = kt * FBK;
        __syncthreads();
        {
            const int r = tid >> 2;
            const int cb = (tid & 3) * 16;
            #pragma unroll
            for (int j = 0; j < 4; j++) {
                *(float4*)&Ks[r * PADK + cb + j * 4] =
                    *(const float4*)(Kb + (size_t)(k0 + r) * DHEAD + cb + j * 4);
                *(float4*)&Vs[r * PADV + cb + j * 4] =
                    *(const float4*)(Vb + (size_t)(k0 + r) * DHEAD + cb + j * 4);
            }
        }
        __syncthreads();

        float sfr[8][4];
        #pragma unroll
        for (int nt = 0; nt < 8; nt++)
            #pragma unroll
            for (int c = 0; c < 4; c++) sfr[nt][c] = 0.0f;

        #pragma unroll
        for (int kc = 0; kc < 8; kc++) {
            const int kk = kc * 8 + ti;
            uint32_t af[4];
            af[0] = __float_as_uint(Qs[(w * 16 + gi) * PADK + kk]);
            af[1] = __float_as_uint(Qs[(w * 16 + gi + 8) * PADK + kk]);
            af[2] = __float_as_uint(Qs[(w * 16 + gi) * PADK + kk + 4]);
            af[3] = __float_as_uint(Qs[(w * 16 + gi + 8) * PADK + kk + 4]);
            #pragma unroll
            for (int nt = 0; nt < 8; nt++) {
                uint32_t bf[2];
                bf[0] = __float_as_uint(Ks[(nt * 8 + gi) * PADK + kk]);
                bf[1] = __float_as_uint(Ks[(nt * 8 + gi) * PADK + kk + 4]);
                mma_tf32(sfr[nt], af, bf);
            }
        }

        if (k0 + FBK - 1 > wq0) {
            const int r0 = wq0 + gi, r1 = wq0 + gi + 8;
            #pragma unroll
            for (int nt = 0; nt < 8; nt++) {
                const int col = k0 + nt * 8 + 2 * ti;
                if (col > r0)     sfr[nt][0] = -1e30f;
                if (col + 1 > r0) sfr[nt][1] = -1e30f;
                if (col > r1)     sfr[nt][2] = -1e30f;
                if (col + 1 > r1) sfr[nt][3] = -1e30f;
            }
        }

        float mx0 = -1e30f, mx1 = -1e30f;
        #pragma unroll
        for (int nt = 0; nt < 8; nt++) {
            mx0 = fmaxf(mx0, fmaxf(sfr[nt][0], sfr[nt][1]));
            mx1 = fmaxf(mx1, fmaxf(sfr[nt][2], sfr[nt][3]));
        }
        #pragma unroll
        for (int off = 1; off < 4; off <<= 1) {
            mx0 = fmaxf(mx0, __shfl_xor_sync(0xffffffffu, mx0, off));
            mx1 = fmaxf(mx1, __shfl_xor_sync(0xffffffffu, mx1, off));
        }
        const float mn0 = fmaxf(m0, mx0), mn1 = fmaxf(m1, mx1);
        const float al0 = __expf(m0 - mn0), al1 = __expf(m1 - mn1);
        m0 = mn0; m1 = mn1;

        float s0 = 0.0f, s1 = 0.0f;
        #pragma unroll
        for (int nt = 0; nt < 8; nt++) {
            sfr[nt][0] = __expf(sfr[nt][0] - mn0);
            sfr[nt][1] = __expf(sfr[nt][1] - mn0);
            sfr[nt][2] = __expf(sfr[nt][2] - mn1);
            sfr[nt][3] = __expf(sfr[nt][3] - mn1);
            s0 += sfr[nt][0] + sfr[nt][1];
            s1 += sfr[nt][2] + sfr[nt][3];
        }
        #pragma unroll
        for (int off = 1; off < 4; off <<= 1) {
            s0 += __shfl_xor_sync(0xffffffffu, s0, off);
            s1 += __shfl_xor_sync(0xffffffffu, s1, off);
        }
        l0 = l0 * al0 + s0;
        l1 = l1 * al1 + s1;
        #pragma unroll
        for (int nt = 0; nt < 8; nt++) {
            oacc[nt][0] *= al0; oacc[nt][1] *= al0;
            oacc[nt][2] *= al1; oacc[nt][3] *= al1;
        }

        #pragma unroll
        for (int nt = 0; nt < 8; nt++) {
            *(float2*)&Pw[gi * PADK + nt * 8 + 2 * ti] =
                make_float2(tf32r(sfr[nt][0]), tf32r(sfr[nt][1]));
            *(float2*)&Pw[(gi + 8) * PADK + nt * 8 + 2 * ti] =
                make_float2(tf32r(sfr[nt][2]), tf32r(sfr[nt][3]));
        }
        __syncwarp();

        #pragma unroll
        for (int kc = 0; kc < 8; kc++) {
            const int kk = kc * 8 + ti;
            uint32_t af[4];
            af[0] = __float_as_uint(Pw[gi * PADK + kk]);
            af[1] = __float_as_uint(Pw[(gi + 8) * PADK + kk]);
            af[2] = __float_as_uint(Pw[gi * PADK + kk + 4]);
            af[3] = __float_as_uint(Pw[(gi + 8) * PADK + kk + 4]);
            #pragma unroll
            for (int nt = 0; nt < 8; nt++) {
                uint32_t bf[2];
                bf[0] = __float_as_uint(Vs[kk * PADV + nt * 8 + gi]);
                bf[1] = __float_as_uint(Vs[(kk + 4) * PADV + nt * 8 + gi]);
                mma_tf32(oacc[nt], af, bf);
            }
        }
        __syncwarp();
    }

    // Normalize + store fp16 to g_Ah[b][s][h*64+d] (feeds fp16 out GEMM)
    const int b = bh >> 4, h = bh & 15;
    const float inv0 = 1.0f / l0, inv1 = 1.0f / l1;
    const int r0 = q0 + w * 16 + gi, r1 = r0 + 8;
    __half2* base0 = (__half2*)(g_Ah + ((size_t)(b * SEQ + r0)) * DMODEL + h * DHEAD);
    __half2* base1 = (__half2*)(g_Ah + ((size_t)(b * SEQ + r1)) * DMODEL + h * DHEAD);
    #pragma unroll
    for (int nt = 0; nt < 8; nt++) {
        const int cp = nt * 4 + ti;   // __half2 index: col/2
        base0[cp] = __floats2half2_rn(oacc[nt][0] * inv0, oacc[nt][1] * inv0);
        base1[cp] = __floats2half2_rn(oacc[nt][2] * inv1, oacc[nt][3] * inv1);
    }
}

// ---------------------------------------------------------------------------

extern "C" void kernel_launch(void* const* d_in, const int* in_sizes, int n_in,
                              void* d_out, int out_size)
{
    const float* x  = (const float*)d_in[0];
    const float* Wq = (const float*)d_in[1];
    const float* Wk = (const float*)d_in[2];
    const float* Wv = (const float*)d_in[3];
    const float* Wo = (const float*)d_in[4];
    float* out = (float*)d_out;

    cudaFuncSetAttribute(gemm_fp16<0>, cudaFuncAttributeMaxDynamicSharedMemorySize, GSM_BYTES);
    cudaFuncSetAttribute(gemm_fp16<1>, cudaFuncAttributeMaxDynamicSharedMemorySize, GSM_BYTES);
    cudaFuncSetAttribute(flash_tc, cudaFuncAttributeMaxDynamicSharedMemorySize,
                         FLASH_SMEM_FLOATS * (int)sizeof(float));

    round_pass<<<(unsigned)((RP_TOTAL + 255) / 256), 256>>>(
        (const float4*)x, (const float4*)Wq, (const float4*)Wk,
        (const float4*)Wv, (const float4*)Wo);

    dim3 g1(DMODEL / 128, (BATCH * SEQ) / 128, 3);
    gemm_fp16<0><<<g1, 256, GSM_BYTES>>>(nullptr);

    flash_tc<<<dim3(SEQ / FBQ, BATCH * NHEAD), 256,
               FLASH_SMEM_FLOATS * (int)sizeof(float)>>>();

    dim3 g2(DMODEL / 128, (BATCH * SEQ) / 128, 1);
    gemm_fp16<1><<<g2, 256, GSM_BYTES>>>(out);
}

// round 16
// speedup vs baseline: 1.9100x; 1.4141x over previous
#include <cuda_runtime.h>
#include <cuda_fp16.h>
#include <stdint.h>
#include <math.h>

// Problem constants: B=4, S=2048, D=1024, H=16, dh=64
#define BATCH 4
#define SEQ   2048
#define DMODEL 1024
#define NHEAD 16
#define DHEAD 64

// Scratch (alloc-free rule: __device__ globals)
__device__ __half g_Qh[(size_t)BATCH * NHEAD * SEQ * DHEAD]; // [b][h][s][d] fp16
__device__ __half g_Kh[(size_t)BATCH * NHEAD * SEQ * DHEAD];
__device__ __half g_Vh[(size_t)BATCH * NHEAD * SEQ * DHEAD];
__device__ __half g_Ah[(size_t)BATCH * SEQ * DMODEL];        // attn out, fp16
__device__ __half g_Xh[(size_t)BATCH * SEQ * DMODEL];        // fp16-rounded x
__device__ __half g_Wqh[(size_t)DMODEL * DMODEL];
__device__ __half g_Wkh[(size_t)DMODEL * DMODEL];
__device__ __half g_Wvh[(size_t)DMODEL * DMODEL];
__device__ __half g_Woh[(size_t)DMODEL * DMODEL];

// ---------------------------------------------------------------------------
// Helpers
// ---------------------------------------------------------------------------
__device__ __forceinline__ void cp16(uint32_t dst, const void* src) {
    asm volatile("cp.async.cg.shared.global [%0], [%1], 16;" :: "r"(dst), "l"(src));
}

__device__ __forceinline__ void mma_f16(float c[4], const uint32_t a[4],
                                        const uint32_t b[2]) {
    asm volatile(
        "mma.sync.aligned.m16n8k16.row.col.f32.f16.f16.f32 "
        "{%0,%1,%2,%3}, {%4,%5,%6,%7}, {%8,%9}, {%0,%1,%2,%3};"
        : "+f"(c[0]), "+f"(c[1]), "+f"(c[2]), "+f"(c[3])
        : "r"(a[0]), "r"(a[1]), "r"(a[2]), "r"(a[3]), "r"(b[0]), "r"(b[1]));
}

__device__ __forceinline__ uint32_t smem_u32(const void* p) {
    uint32_t a;
    asm("{ .reg .u64 u; cvta.to.shared.u64 u, %1; cvt.u32.u64 %0, u; }"
        : "=r"(a) : "l"(p));
    return a;
}

// ---------------------------------------------------------------------------
// Pre-round pass: x + 4 weights -> fp16(RN) scratch.
// ---------------------------------------------------------------------------
#define XR_F4 ((size_t)BATCH * SEQ * DMODEL / 4)
#define W_F4  ((size_t)DMODEL * DMODEL / 4)
#define RP_TOTAL (XR_F4 + 4 * W_F4)

__global__ __launch_bounds__(256) void round_pass(
    const float4* __restrict__ x,  const float4* __restrict__ wq,
    const float4* __restrict__ wk, const float4* __restrict__ wv,
    const float4* __restrict__ wo)
{
    size_t i = (size_t)blockIdx.x * blockDim.x + threadIdx.x;
    if (i >= RP_TOTAL) return;
    const float4* src; __half2* dst; size_t j;
    if (i < XR_F4)                { src = x;  dst = (__half2*)g_Xh;  j = i; }
    else {
        size_t k = i - XR_F4; int sel = (int)(k / W_F4); j = k % W_F4;
        src = (sel == 0) ? wq : (sel == 1) ? wk : (sel == 2) ? wv : wo;
        dst = (__half2*)((sel == 0) ? g_Wqh : (sel == 1) ? g_Wkh
                        : (sel == 2) ? g_Wvh : g_Woh);
    }
    float4 v = src[j];
    dst[j * 2]     = __floats2half2_rn(v.x, v.y);
    dst[j * 2 + 1] = __floats2half2_rn(v.z, v.w);
}

// ---------------------------------------------------------------------------
// FP16 mma.sync GEMM (R15-proven): C[m][n] = sum_k A[m][k] * W[n][k]
// 128x128 tile, BK=64 halfs, 8 warps 2m x 4n, m16n8k16.
// MODE 0: z selects Wq/Wk/Wv; epilogue fuses RoPE (z<2), stores fp16 to
//         g_Qh/g_Kh/g_Vh [b][h][s][dh]. MODE 1: A=g_Ah, W=g_Woh, fp32 out.
// ---------------------------------------------------------------------------
#define GSM_BYTES 65536

template <int MODE>
__global__ __launch_bounds__(256) void gemm_fp16(float* __restrict__ Cout)
{
    extern __shared__ uint32_t gsm32[];
    const int z = (MODE == 0) ? blockIdx.z : 0;
    const __half* Ain = (MODE == 0) ? g_Xh : g_Ah;
    const __half* W = (MODE == 0) ? ((z == 0) ? g_Wqh : (z == 1) ? g_Wkh : g_Wvh)
                                  : g_Woh;
    __half* OutH = (MODE == 0) ? ((z == 0) ? g_Qh : (z == 1) ? g_Kh : g_Vh) : nullptr;

    const int m0 = blockIdx.y * 128, n0 = blockIdx.x * 128;
    const int t = threadIdx.x;
    const int lane = t & 31, wid = t >> 5;
    const int wm = wid >> 2, wn = wid & 3;
    const int gi = lane >> 2, ti = lane & 3;

    uint32_t* Ab[2] = {gsm32, gsm32 + 8192};
    uint32_t* Bb[2] = {gsm32 + 4096, gsm32 + 12288};
    const uint32_t sb = smem_u32(gsm32);
    const uint32_t aoff0 = sb, aoff1 = sb + 32768u;
    const uint32_t boff0 = sb + 16384u, boff1 = sb + 49152u;

    const int rr = t >> 3, cg = t & 7;
    const __half* Ag = Ain + (size_t)(m0 + rr) * DMODEL + cg * 8;
    const __half* Bg = W + (size_t)(n0 + rr) * DMODEL + cg * 8;
    const uint32_t dsw = (uint32_t)(rr * 32 + ((cg ^ (rr & 7)) << 2)) * 4;

    int aBase[4], bBase[4];
    #pragma unroll
    for (int mi = 0; mi < 4; mi++) aBase[mi] = (wm * 64 + mi * 16 + gi) * 32 + ti;
    #pragma unroll
    for (int ni = 0; ni < 4; ni++) bBase[ni] = (wn * 32 + ni * 8 + gi) * 32 + ti;

    float acc[4][4][4];
    #pragma unroll
    for (int mi = 0; mi < 4; mi++)
        #pragma unroll
        for (int ni = 0; ni < 4; ni++)
            #pragma unroll
            for (int c = 0; c < 4; c++) acc[mi][ni][c] = 0.0f;

    auto stage = [&](int buf, int kt) {
        const __half* ag = Ag + kt * 64;
        const __half* bg = Bg + kt * 64;
        uint32_t ad = (buf ? aoff1 : aoff0) + dsw;
        uint32_t bd = (buf ? boff1 : boff0) + dsw;
        #pragma unroll
        for (int i = 0; i < 4; i++) {
            cp16(ad + i * 4096, ag + (size_t)i * 32 * DMODEL);
            cp16(bd + i * 4096, bg + (size_t)i * 32 * DMODEL);
        }
        asm volatile("cp.async.commit_group;");
    };

    stage(0, 0);
    for (int kt = 0; kt < DMODEL / 64; kt++) {
        const int buf = kt & 1;
        asm volatile("cp.async.wait_group 0;");
        __syncthreads();
        if (kt < DMODEL / 64 - 1) stage(buf ^ 1, kt + 1);

        const uint32_t* Sa = Ab[buf];
        const uint32_t* Sb = Bb[buf];
        #pragma unroll
        for (int ks = 0; ks < 4; ks++) {
            const int s0 = ((2 * ks) ^ gi) << 2;
            const int s1 = ((2 * ks + 1) ^ gi) << 2;
            uint32_t af[4][4];
            #pragma unroll
            for (int mi = 0; mi < 4; mi++) {
                af[mi][0] = Sa[aBase[mi] + s0];
                af[mi][1] = Sa[aBase[mi] + 256 + s0];
                af[mi][2] = Sa[aBase[mi] + s1];
                af[mi][3] = Sa[aBase[mi] + 256 + s1];
            }
            uint32_t bf[4][2];
            #pragma unroll
            for (int ni = 0; ni < 4; ni++) {
                bf[ni][0] = Sb[bBase[ni] + s0];
                bf[ni][1] = Sb[bBase[ni] + s1];
            }
            #pragma unroll
            for (int mi = 0; mi < 4; mi++)
                #pragma unroll
                for (int ni = 0; ni < 4; ni++)
                    mma_f16(acc[mi][ni], af[mi], bf[ni]);
        }
    }

    #pragma unroll
    for (int mi = 0; mi < 4; mi++) {
        #pragma unroll
        for (int ni = 0; ni < 4; ni++) {
            const int row = m0 + wm * 64 + mi * 16 + gi;
            const int col = n0 + wn * 32 + ni * 8 + 2 * ti;
            const float c0 = acc[mi][ni][0], c1 = acc[mi][ni][1];
            const float c2 = acc[mi][ni][2], c3 = acc[mi][ni][3];
            if (MODE == 1) {
                *(float2*)(Cout + (size_t)row * DMODEL + col) = make_float2(c0, c1);
                *(float2*)(Cout + (size_t)(row + 8) * DMODEL + col) = make_float2(c2, c3);
            } else {
                const int h = col >> 6, dq = col & 63;
                const int s0 = row & (SEQ - 1), bb = row >> 11;
                __half* d0 = OutH + (((size_t)(bb * NHEAD + h) * SEQ + s0) * DHEAD + dq);
                __half* d1 = d0 + 8 * DHEAD;
                if (z < 2) {
                    const int fi = dq >> 1;
                    const float inv = exp2f(-0.41524101186092356f * (float)fi);
                    float sn, cs;
                    sincosf((float)s0 * inv, &sn, &cs);
                    *(__half2*)d0 = __floats2half2_rn(c0 * cs - c1 * sn,
                                                      c0 * sn + c1 * cs);
                    sincosf((float)(s0 + 8) * inv, &sn, &cs);
                    *(__half2*)d1 = __floats2half2_rn(c2 * cs - c3 * sn,
                                                      c2 * sn + c3 * cs);
                } else {
                    *(__half2*)d0 = __floats2half2_rn(c0, c1);
                    *(__half2*)d1 = __floats2half2_rn(c2, c3);
                }
            }
        }
    }
}

// ---------------------------------------------------------------------------
// FP16 tensor-core flash attention. BQ=128 (8 warps x 16 q), BK=64,
// m16n8k16, fp32 accum/softmax. Smem (halfs, stride PADH=72):
//   Qs[128], Ks[64] key-major; Vt[64] d-major (transposed at staging);
//   Ps[8][16] per-warp P (fp16). 55296 B -> 2 CTAs/SM.
// ---------------------------------------------------------------------------
#define FBQ 128
#define FBK 64
#define PADH 72
#define FLASH_SMEM_BYTES ((128 + 64 + 64 + 128) * PADH * 2)

__global__ __launch_bounds__(256, 2) void flash_fp16()
{
    extern __shared__ __half smh[];
    __half* Qs = smh;                      // [128][72]
    __half* Ks = Qs + 128 * PADH;          // [64][72]  (key-major)
    __half* Vt = Ks + 64 * PADH;           // [64][72]  (d-major: Vt[d][key])
    __half* Ps = Vt + 64 * PADH;           // [8][16][72]

    const int qt = (int)gridDim.x - 1 - (int)blockIdx.x;   // heavy blocks first
    const int bh = blockIdx.y;
    const __half* Qb = g_Qh + (size_t)bh * SEQ * DHEAD;
    const __half* Kb = g_Kh + (size_t)bh * SEQ * DHEAD;
    const __half* Vb = g_Vh + (size_t)bh * SEQ * DHEAD;

    const int tid = threadIdx.x;
    const int lane = tid & 31, w = tid >> 5;
    const int gi = lane >> 2, ti = lane & 3;
    const int q0 = qt * FBQ;
    const int wq0 = q0 + w * 16;
    __half* Pw = Ps + w * 16 * PADH;

    // Load Q tile, scaled by 1/8 (exact in fp16)
    {
        const int r = tid >> 1;
        const int gq = (tid & 1) * 4;          // 4 groups of 8 halfs
        const __half2 sc = __float2half2_rn(0.125f);
        #pragma unroll
        for (int j = 0; j < 4; j++) {
            uint4 v = *(const uint4*)(Qb + (size_t)(q0 + r) * DHEAD + (gq + j) * 8);
            __half2* h2 = (__half2*)&v;
            h2[0] = __hmul2(h2[0], sc); h2[1] = __hmul2(h2[1], sc);
            h2[2] = __hmul2(h2[2], sc); h2[3] = __hmul2(h2[3], sc);
            *(uint4*)&Qs[r * PADH + (gq + j) * 8] = v;
        }
    }

    float oacc[8][4];
    #pragma unroll
    for (int nt = 0; nt < 8; nt++)
        #pragma unroll
        for (int c = 0; c < 4; c++) oacc[nt][c] = 0.0f;
    float m0 = -1e30f, m1 = -1e30f, l0 = 0.0f, l1 = 0.0f;

    const int nkt = 2 * (qt + 1);
    for (int kt = 0; kt < nkt; kt++) {
        const int k0 = kt * FBK;
        __syncthreads();
        {
            const int r = tid >> 2;            // key 0..63
            const int g2 = (tid & 3) * 2;      // 2 groups of 8 halfs
            #pragma unroll
            for (int j = 0; j < 2; j++) {
                const int g = g2 + j;
                uint4 kv = *(const uint4*)(Kb + (size_t)(k0 + r) * DHEAD + g * 8);
                *(uint4*)&Ks[r * PADH + g * 8] = kv;
                uint4 vv = *(const uint4*)(Vb + (size_t)(k0 + r) * DHEAD + g * 8);
                const __half* vh = (const __half*)&vv;
                #pragma unroll
                for (int e = 0; e < 8; e++)
                    Vt[(g * 8 + e) * PADH + r] = vh[e];
            }
        }
        __syncthreads();

        // S = Q @ K^T  (16 x 64 per warp), fp16 MMA
        float sfr[8][4];
        #pragma unroll
        for (int nt = 0; nt < 8; nt++)
            #pragma unroll
            for (int c = 0; c < 4; c++) sfr[nt][c] = 0.0f;

        #pragma unroll
        for (int kc = 0; kc < 4; kc++) {
            const int kb = kc * 16 + 2 * ti;
            uint32_t af[4];
            af[0] = *(uint32_t*)&Qs[(w * 16 + gi) * PADH + kb];
            af[1] = *(uint32_t*)&Qs[(w * 16 + gi + 8) * PADH + kb];
            af[2] = *(uint32_t*)&Qs[(w * 16 + gi) * PADH + kb + 8];
            af[3] = *(uint32_t*)&Qs[(w * 16 + gi + 8) * PADH + kb + 8];
            #pragma unroll
            for (int nt = 0; nt < 8; nt++) {
                uint32_t bf[2];
                bf[0] = *(uint32_t*)&Ks[(nt * 8 + gi) * PADH + kb];
                bf[1] = *(uint32_t*)&Ks[(nt * 8 + gi) * PADH + kb + 8];
                mma_f16(sfr[nt], af, bf);
            }
        }

        // Causal mask
        if (k0 + FBK - 1 > wq0) {
            const int r0 = wq0 + gi, r1 = wq0 + gi + 8;
            #pragma unroll
            for (int nt = 0; nt < 8; nt++) {
                const int col = k0 + nt * 8 + 2 * ti;
                if (col > r0)     sfr[nt][0] = -1e30f;
                if (col + 1 > r0) sfr[nt][1] = -1e30f;
                if (col > r1)     sfr[nt][2] = -1e30f;
                if (col + 1 > r1) sfr[nt][3] = -1e30f;
            }
        }

        // Online softmax (fp32)
        float mx0 = -1e30f, mx1 = -1e30f;
        #pragma unroll
        for (int nt = 0; nt < 8; nt++) {
            mx0 = fmaxf(mx0, fmaxf(sfr[nt][0], sfr[nt][1]));
            mx1 = fmaxf(mx1, fmaxf(sfr[nt][2], sfr[nt][3]));
        }
        #pragma unroll
        for (int off = 1; off < 4; off <<= 1) {
            mx0 = fmaxf(mx0, __shfl_xor_sync(0xffffffffu, mx0, off));
            mx1 = fmaxf(mx1, __shfl_xor_sync(0xffffffffu, mx1, off));
        }
        const float mn0 = fmaxf(m0, mx0), mn1 = fmaxf(m1, mx1);
        const float al0 = __expf(m0 - mn0), al1 = __expf(m1 - mn1);
        m0 = mn0; m1 = mn1;

        float s0 = 0.0f, s1 = 0.0f;
        #pragma unroll
        for (int nt = 0; nt < 8; nt++) {
            sfr[nt][0] = __expf(sfr[nt][0] - mn0);
            sfr[nt][1] = __expf(sfr[nt][1] - mn0);
            sfr[nt][2] = __expf(sfr[nt][2] - mn1);
            sfr[nt][3] = __expf(sfr[nt][3] - mn1);
            s0 += sfr[nt][0] + sfr[nt][1];
            s1 += sfr[nt][2] + sfr[nt][3];
        }
        #pragma unroll
        for (int off = 1; off < 4; off <<= 1) {
            s0 += __shfl_xor_sync(0xffffffffu, s0, off);
            s1 += __shfl_xor_sync(0xffffffffu, s1, off);
        }
        l0 = l0 * al0 + s0;
        l1 = l1 * al1 + s1;
        #pragma unroll
        for (int nt = 0; nt < 8; nt++) {
            oacc[nt][0] *= al0; oacc[nt][1] *= al0;
            oacc[nt][2] *= al1; oacc[nt][3] *= al1;
        }

        // Stage P (fp16) per-warp: Pw[q][key]
        #pragma unroll
        for (int nt = 0; nt < 8; nt++) {
            *(__half2*)&Pw[gi * PADH + nt * 8 + 2 * ti] =
                __floats2half2_rn(sfr[nt][0], sfr[nt][1]);
            *(__half2*)&Pw[(gi + 8) * PADH + nt * 8 + 2 * ti] =
                __floats2half2_rn(sfr[nt][2], sfr[nt][3]);
        }
        __syncwarp();

        // O += P @ V  (A = Pw[q][key], B = Vt[d][key]), fp16 MMA
        #pragma unroll
        for (int kc = 0; kc < 4; kc++) {
            const int kb = kc * 16 + 2 * ti;
            uint32_t af[4];
            af[0] = *(uint32_t*)&Pw[gi * PADH + kb];
            af[1] = *(uint32_t*)&Pw[(gi + 8) * PADH + kb];
            af[2] = *(uint32_t*)&Pw[gi * PADH + kb + 8];
            af[3] = *(uint32_t*)&Pw[(gi + 8) * PADH + kb + 8];
            #pragma unroll
            for (int nt = 0; nt < 8; nt++) {
                uint32_t bf[2];
                bf[0] = *(uint32_t*)&Vt[(nt * 8 + gi) * PADH + kb];
                bf[1] = *(uint32_t*)&Vt[(nt * 8 + gi) * PADH + kb + 8];
                mma_f16(oacc[nt], af, bf);
            }
        }
        __syncwarp();
    }

    // Normalize + store fp16 to g_Ah[b][s][h*64+d]
    const int b = bh >> 4, h = bh & 15;
    const float inv0 = 1.0f / l0, inv1 = 1.0f / l1;
    const int r0 = q0 + w * 16 + gi, r1 = r0 + 8;
    __half2* base0 = (__half2*)(g_Ah + ((size_t)(b * SEQ + r0)) * DMODEL + h * DHEAD);
    __half2* base1 = (__half2*)(g_Ah + ((size_t)(b * SEQ + r1)) * DMODEL + h * DHEAD);
    #pragma unroll
    for (int nt = 0; nt < 8; nt++) {
        const int cp = nt * 4 + ti;
        base0[cp] = __floats2half2_rn(oacc[nt][0] * inv0, oacc[nt][1] * inv0);
        base1[cp] = __floats2half2_rn(oacc[nt][2] * inv1, oacc[nt][3] * inv1);
    }
}

// ---------------------------------------------------------------------------

extern "C" void kernel_launch(void* const* d_in, const int* in_sizes, int n_in,
                              void* d_out, int out_size)
{
    const float* x  = (const float*)d_in[0];
    const float* Wq = (const float*)d_in[1];
    const float* Wk = (const float*)d_in[2];
    const float* Wv = (const float*)d_in[3];
    const float* Wo = (const float*)d_in[4];
    float* out = (float*)d_out;

    cudaFuncSetAttribute(gemm_fp16<0>, cudaFuncAttributeMaxDynamicSharedMemorySize, GSM_BYTES);
    cudaFuncSetAttribute(gemm_fp16<1>, cudaFuncAttributeMaxDynamicSharedMemorySize, GSM_BYTES);
    cudaFuncSetAttribute(flash_fp16, cudaFuncAttributeMaxDynamicSharedMemorySize,
                         FLASH_SMEM_BYTES);

    round_pass<<<(unsigned)((RP_TOTAL + 255) / 256), 256>>>(
        (const float4*)x, (const float4*)Wq, (const float4*)Wk,
        (const float4*)Wv, (const float4*)Wo);

    dim3 g1(DMODEL / 128, (BATCH * SEQ) / 128, 3);
    gemm_fp16<0><<<g1, 256, GSM_BYTES>>>(nullptr);

    flash_fp16<<<dim3(SEQ / FBQ, BATCH * NHEAD), 256, FLASH_SMEM_BYTES>>>();

    dim3 g2(DMODEL / 128, (BATCH * SEQ) / 128, 1);
    gemm_fp16<1><<<g2, 256, GSM_BYTES>>>(out);
}